// round 13
// baseline (speedup 1.0000x reference)
#include <cuda_runtime.h>
#include <cstdint>

#define CH_IN 32
#define CH_Y  16
#define IMG_H 256
#define IMG_W 256
#define NB    16
#define CHS   (IMG_H * IMG_W)   // channel stride (elements)
#define CHS2  (CHS / 2)
#define NT    128               // one (b,h) row; thread = px-pair, full 16 o

union F2U { float2 f; uint64_t u; };

// sm_103a packed dual-fp32 ops
__device__ __forceinline__ void fma2(uint64_t& d, uint64_t a, uint64_t b) {
    asm("fma.rn.f32x2 %0, %1, %2, %0;" : "+l"(d) : "l"(a), "l"(b));
}
__device__ __forceinline__ uint64_t mul2(uint64_t a, uint64_t b) {
    uint64_t d; asm("mul.rn.f32x2 %0, %1, %2;" : "=l"(d) : "l"(a), "l"(b)); return d;
}
__device__ __forceinline__ uint64_t add2(uint64_t a, uint64_t b) {
    uint64_t d; asm("add.rn.f32x2 %0, %1, %2;" : "=l"(d) : "l"(a), "l"(b)); return d;
}
__device__ __forceinline__ uint64_t dup2(float x) {
    uint64_t d; asm("mov.b64 %0, {%1, %1};" : "=l"(d) : "f"(x)); return d;
}
__device__ __forceinline__ uint64_t pack2(float lo, float hi) {
    uint64_t d; asm("mov.b64 %0, {%1, %2};" : "=l"(d) : "f"(lo), "f"(hi)); return d;
}

// R6 structure minus all staging: inputs stream via LDG (c,p DRAM-cold in the
// q/k pass; p re-read in v pass is an L2 hit), concat(c) written through from
// the q/k pass registers. Smem = weights only.
__global__ void __launch_bounds__(NT, 4) cross_attn_kernel(
    const float* __restrict__ cin, const float* __restrict__ pin,
    const float* __restrict__ Wq,  const float* __restrict__ bq,
    const float* __restrict__ Wk,  const float* __restrict__ bk,
    const float* __restrict__ Wv,  const float* __restrict__ bv,
    const float* __restrict__ Wy,  const float* __restrict__ by,
    float* __restrict__ out)
{
    __shared__ __align__(16) float2 wqT[CH_IN * 8];  // [c][o2] natural o-pairs
    __shared__ __align__(16) float2 wkT[CH_IN * 8];
    __shared__ __align__(16) float2 wvT[CH_IN * 8];
    __shared__ __align__(16) float4 wy_s[CH_IN * CH_Y / 4];
    __shared__ float2   bq2[8], bk2[8], bv2[8];
    __shared__ float    by_s[CH_IN];
    __shared__ uint64_t red[4][8];                   // [warp][o2]

    const int tid = threadIdx.x;                     // px-pair index 0..127

    // ---- weight setup: transpose to [c][o2] pair layout (2 entries each) ----
#pragma unroll
    for (int s = 0; s < 2; s++) {
        int i = tid * 2 + s;                         // 0..255
        int c = i >> 3, o2 = i & 7;
        wqT[i] = make_float2(Wq[(2*o2)*CH_IN + c], Wq[(2*o2+1)*CH_IN + c]);
        wkT[i] = make_float2(Wk[(2*o2)*CH_IN + c], Wk[(2*o2+1)*CH_IN + c]);
        wvT[i] = make_float2(Wv[(2*o2)*CH_IN + c], Wv[(2*o2+1)*CH_IN + c]);
    }
    wy_s[tid] = ((const float4*)Wy)[tid];            // o contiguous in rows
    if (tid < 8) {
        bq2[tid] = make_float2(bq[2*tid], bq[2*tid+1]);
        bk2[tid] = make_float2(bk[2*tid], bk[2*tid+1]);
        bv2[tid] = make_float2(bv[2*tid], bv[2*tid+1]);
    }
    if (tid < CH_IN) by_s[tid] = by[tid];
    __syncthreads();

    const int h = blockIdx.x & (IMG_H - 1);
    const int b = blockIdx.x >> 8;
    const size_t base = (size_t)b * CH_IN * CHS + (size_t)h * IMG_W;

    const float2* cp2 = (const float2*)(cin + base); // + ch*CHS2 + tid
    const float2* pp2 = (const float2*)(pin + base);
    float2* oy2 = (float2*)(out + (size_t)b * 2 * CH_IN * CHS + (size_t)h * IMG_W);
    float2* oc2 = oy2 + (size_t)CH_IN * CHS2;        // concat(c) half

    // ---------------- q,k projection: direct-stream inputs ----------------
    uint64_t q[2][8], k[2][8];        // [px][o2] packed (o 2o2, 2o2+1)
#pragma unroll
    for (int o2 = 0; o2 < 8; o2++) {
        F2U tq; tq.f = bq2[o2]; q[0][o2] = tq.u; q[1][o2] = tq.u;
        F2U tk; tk.f = bk2[o2]; k[0][o2] = tk.u; k[1][o2] = tk.u;
    }

#pragma unroll
    for (int c4 = 0; c4 < CH_IN / 4; c4++) {
        float2 cv[4], pv[4];
#pragma unroll
        for (int j = 0; j < 4; j++) {
            int ch = c4 * 4 + j;
            cv[j] = cp2[(size_t)ch * CHS2 + tid];    // DRAM stream (first touch)
            pv[j] = pp2[(size_t)ch * CHS2 + tid];
        }
#pragma unroll
        for (int j = 0; j < 4; j++)                  // concat write-through
            oc2[(size_t)(c4 * 4 + j) * CHS2 + tid] = cv[j];
#pragma unroll
        for (int j = 0; j < 4; j++) {
            const int ch = c4 * 4 + j;
            const ulonglong2* wq2 = (const ulonglong2*)&wqT[ch * 8];
            const ulonglong2* wk2 = (const ulonglong2*)&wkT[ch * 8];
            uint64_t cd0 = dup2(cv[j].x), cd1 = dup2(cv[j].y);
            uint64_t pd0 = dup2(pv[j].x), pd1 = dup2(pv[j].y);
#pragma unroll
            for (int m = 0; m < 4; m++) {            // 2 o-pairs per LDS.128
                ulonglong2 a = wq2[m];
                fma2(q[0][2*m+0], a.x, cd0); fma2(q[0][2*m+1], a.y, cd0);
                fma2(q[1][2*m+0], a.x, cd1); fma2(q[1][2*m+1], a.y, cd1);
                ulonglong2 bm = wk2[m];
                fma2(k[0][2*m+0], bm.x, pd0); fma2(k[0][2*m+1], bm.y, pd0);
                fma2(k[1][2*m+0], bm.x, pd1); fma2(k[1][2*m+1], bm.y, pd1);
            }
        }
    }

    // exp(q*k). No max-subtraction: |q*k| O(1..10); fp32 exp safe, identical
    // after normalization.
    uint64_t e[2][8];
#pragma unroll
    for (int px = 0; px < 2; px++)
#pragma unroll
        for (int o2 = 0; o2 < 8; o2++) {
            F2U pr; pr.u = mul2(q[px][o2], k[px][o2]);
            e[px][o2] = pack2(__expf(pr.f.x), __expf(pr.f.y));
        }

    // ---------------- softmax over width (block reduction) ----------------
    const int lane = tid & 31;
    const int wrp  = tid >> 5;
#pragma unroll
    for (int o2 = 0; o2 < 8; o2++) {
        uint64_t s = add2(e[0][o2], e[1][o2]);
#pragma unroll
        for (int d = 16; d > 0; d >>= 1)
            s = add2(s, __shfl_xor_sync(0xffffffffu, (unsigned long long)s, d));
        if (lane == 0) red[wrp][o2] = s;
    }
    __syncthreads();

#pragma unroll
    for (int o2 = 0; o2 < 8; o2++) {
        F2U tot; tot.u = add2(add2(red[0][o2], red[1][o2]),
                              add2(red[2][o2], red[3][o2]));
        uint64_t inv = pack2(__frcp_rn(tot.f.x), __frcp_rn(tot.f.y));
        e[0][o2] = mul2(e[0][o2], inv);              // fold 1/sum into e
        e[1][o2] = mul2(e[1][o2], inv);
    }

    // ---------------- v projection: p re-read = guaranteed L2 hit ----------
    {
        uint64_t v[2][8];
#pragma unroll
        for (int o2 = 0; o2 < 8; o2++) {
            F2U tv; tv.f = bv2[o2]; v[0][o2] = tv.u; v[1][o2] = tv.u;
        }
#pragma unroll
        for (int c4 = 0; c4 < CH_IN / 4; c4++) {
            float2 pv[4];
#pragma unroll
            for (int j = 0; j < 4; j++)
                pv[j] = pp2[(size_t)(c4 * 4 + j) * CHS2 + tid];
#pragma unroll
            for (int j = 0; j < 4; j++) {
                const int ch = c4 * 4 + j;
                const ulonglong2* wv2 = (const ulonglong2*)&wvT[ch * 8];
                uint64_t pd0 = dup2(pv[j].x), pd1 = dup2(pv[j].y);
#pragma unroll
                for (int m = 0; m < 4; m++) {
                    ulonglong2 a = wv2[m];
                    fma2(v[0][2*m+0], a.x, pd0); fma2(v[0][2*m+1], a.y, pd0);
                    fma2(v[1][2*m+0], a.x, pd1); fma2(v[1][2*m+1], a.y, pd1);
                }
            }
        }
#pragma unroll
        for (int px = 0; px < 2; px++)
#pragma unroll
            for (int o2 = 0; o2 < 8; o2++)
                e[px][o2] = mul2(e[px][o2], v[px][o2]);   // y = softmax * v
    }

    // ---------------- output conv1x1 ----------------
    const ulonglong2* wyu2 = (const ulonglong2*)wy_s;     // 4 per ic, o-pairs
#pragma unroll
    for (int ic = 0; ic < CH_IN; ic++) {
        uint64_t acc0 = pack2(by_s[ic], 0.f);
        uint64_t acc1 = acc0;
#pragma unroll
        for (int m = 0; m < 4; m++) {
            ulonglong2 w = wyu2[ic * 4 + m];              // o-pairs (2m, 2m+1)
            fma2(acc0, w.x, e[0][2*m+0]); fma2(acc0, w.y, e[0][2*m+1]);
            fma2(acc1, w.x, e[1][2*m+0]); fma2(acc1, w.y, e[1][2*m+1]);
        }
        F2U r0, r1; r0.u = acc0; r1.u = acc1;
        oy2[(size_t)ic * CHS2 + tid] = make_float2(r0.f.x + r0.f.y,
                                                   r1.f.x + r1.f.y);
    }
}

extern "C" void kernel_launch(void* const* d_in, const int* in_sizes, int n_in,
                              void* d_out, int out_size)
{
    cross_attn_kernel<<<NB * IMG_H, NT>>>(
        (const float*)d_in[0],  // c
        (const float*)d_in[1],  // p
        (const float*)d_in[2],  // Wq
        (const float*)d_in[3],  // bq
        (const float*)d_in[4],  // Wk
        (const float*)d_in[5],  // bk
        (const float*)d_in[6],  // Wv
        (const float*)d_in[7],  // bv
        (const float*)d_in[8],  // Wy
        (const float*)d_in[9],  // by
        (float*)d_out);
}